// round 17
// baseline (speedup 1.0000x reference)
#include <cuda_runtime.h>
#include <cuda_fp16.h>
#include <math.h>
#include <stdint.h>

#define D_    1024
#define S_    1024
#define BB_   2
#define NTOK  2048
#define NH_   16
#define DH_   64
#define E_    8
#define KSEL  2
#define FF_   4096
#define NSLOT 4096

#define BKH   64
#define ASTH  72
#define ASZB  (128*ASTH*2)
#define NSTG  3             // hgemm stages (2 CTA/SM constraint)
#define MSTG  4             // moe stages (1 CTA/SM)

__device__ __half g_xn[NTOK * D_];
__device__ __half g_wqkvh[3 * D_ * D_];
__device__ __half g_woh[D_ * D_];
__device__ __half g_w1h[(size_t)E_ * D_ * FF_];
__device__ __half g_w2h[(size_t)E_ * FF_ * D_];
__device__ __half g_qkv[3 * NTOK * D_];
__device__ __half g_probsH[(size_t)BB_ * NH_ * S_ * S_];
__device__ float  g_rowsum[BB_ * NH_ * S_];
__device__ __half g_attnout[NTOK * D_];
__device__ float  g_x2[NTOK * D_];
__device__ __half g_htf[NTOK * D_];
__device__ __half g_act[(size_t)NSLOT * FF_];
__device__ __half g_y[(size_t)NSLOT * D_];
__device__ float g_topval[NTOK * KSEL];
__device__ int   g_topidx[NTOK * KSEL];
__device__ int   g_slotof[NTOK * KSEL];
__device__ int   g_perm[NSLOT];
__device__ int   g_counts[E_];
__device__ int   g_offs[E_ + 1];
__device__ int   g_cursor[E_];
__device__ float g_probsum[E_];

__device__ __forceinline__ float gelu_tanh(float v) {
    float v3 = v * v * v;
    return 0.5f * v * (1.f + tanhf(0.7978845608028654f * (v + 0.044715f * v3)));
}
__device__ __forceinline__ void cpa16(unsigned dst, const void* src, bool p) {
    int sz = p ? 16 : 0;
    asm volatile("cp.async.cg.shared.global [%0], [%1], 16, %2;\n"
                 :: "r"(dst), "l"(src), "r"(sz));
}
__device__ __forceinline__ void cp_commit() { asm volatile("cp.async.commit_group;\n"); }
__device__ __forceinline__ void ldsm4(unsigned& r0, unsigned& r1, unsigned& r2, unsigned& r3,
                                      unsigned addr) {
    asm volatile("ldmatrix.sync.aligned.m8n8.x4.shared.b16 {%0,%1,%2,%3}, [%4];"
                 : "=r"(r0), "=r"(r1), "=r"(r2), "=r"(r3) : "r"(addr));
}
__device__ __forceinline__ void ldsm4t(unsigned& r0, unsigned& r1, unsigned& r2, unsigned& r3,
                                       unsigned addr) {
    asm volatile("ldmatrix.sync.aligned.m8n8.x4.trans.shared.b16 {%0,%1,%2,%3}, [%4];"
                 : "=r"(r0), "=r"(r1), "=r"(r2), "=r"(r3) : "r"(addr));
}
__device__ __forceinline__ void mma16816(float* d, const unsigned* a, const unsigned* b) {
    asm volatile(
        "mma.sync.aligned.m16n8k16.row.col.f32.f16.f16.f32 "
        "{%0,%1,%2,%3}, {%4,%5,%6,%7}, {%8,%9}, {%0,%1,%2,%3};"
        : "+f"(d[0]), "+f"(d[1]), "+f"(d[2]), "+f"(d[3])
        : "r"(a[0]), "r"(a[1]), "r"(a[2]), "r"(a[3]), "r"(b[0]), "r"(b[1]));
}

__global__ void init2_kernel() {
    int i = blockIdx.x * 512 + threadIdx.x;
    if (i < E_) { g_counts[i] = 0; g_cursor[i] = 0; g_probsum[i] = 0.f; }
    if (i < BB_ * NH_ * S_) g_rowsum[i] = 0.f;
}

__global__ void f2h_kernel(const float4* __restrict__ in, uint4* __restrict__ out,
                           long long n8) {
    for (long long i = blockIdx.x * 256LL + threadIdx.x; i < n8;
         i += (long long)gridDim.x * 256) {
        float4 a = in[2 * i], b = in[2 * i + 1];
        __half2 h0 = __floats2half2_rn(a.x, a.y);
        __half2 h1 = __floats2half2_rn(a.z, a.w);
        __half2 h2 = __floats2half2_rn(b.x, b.y);
        __half2 h3 = __floats2half2_rn(b.z, b.w);
        uint4 o;
        o.x = *(unsigned*)&h0; o.y = *(unsigned*)&h1;
        o.z = *(unsigned*)&h2; o.w = *(unsigned*)&h3;
        out[i] = o;
    }
}
__global__ void f2h4_kernel(const float4* __restrict__ a, const float4* __restrict__ b,
                            const float4* __restrict__ c, const float4* __restrict__ d,
                            uint4* __restrict__ oqkv, uint4* __restrict__ oo) {
    const float4* src[4] = { a, b, c, d };
    long long n8 = (long long)D_ * D_ / 8;
    uint4* dst;
    int z = blockIdx.y;
    if (z < 3) dst = oqkv + (size_t)z * n8;
    else       dst = oo;
    const float4* in = src[z];
    for (long long i = blockIdx.x * 256LL + threadIdx.x; i < n8;
         i += (long long)gridDim.x * 256) {
        float4 va = in[2 * i], vb = in[2 * i + 1];
        __half2 h0 = __floats2half2_rn(va.x, va.y);
        __half2 h1 = __floats2half2_rn(va.z, va.w);
        __half2 h2 = __floats2half2_rn(vb.x, vb.y);
        __half2 h3 = __floats2half2_rn(vb.z, vb.w);
        uint4 o;
        o.x = *(unsigned*)&h0; o.y = *(unsigned*)&h1;
        o.z = *(unsigned*)&h2; o.w = *(unsigned*)&h3;
        dst[i] = o;
    }
}
__global__ void rmsnorm_kernel(const float* __restrict__ X, const float* __restrict__ W,
                               __half* __restrict__ OT) {
    int t = blockIdx.x;
    const float* x = X + (size_t)t * D_;
    float ss = 0.f;
    for (int d = threadIdx.x; d < D_; d += 256) { float v = x[d]; ss += v * v; }
    __shared__ float red[256];
    red[threadIdx.x] = ss; __syncthreads();
    for (int s = 128; s > 0; s >>= 1) {
        if (threadIdx.x < s) red[threadIdx.x] += red[threadIdx.x + s];
        __syncthreads();
    }
    float scale = rsqrtf(red[0] * (1.f / D_) + 1e-6f);
    for (int d = threadIdx.x; d < D_; d += 256)
        OT[(size_t)t * D_ + d] = __float2half_rn(x[d] * scale * W[d]);
}

__global__ void rmsrouter_kernel(const float* __restrict__ X, const float* __restrict__ W,
                                 __half* __restrict__ OT, const float* __restrict__ RW) {
    int t = blockIdx.x;
    int tid = threadIdx.x;
    const float* x = X + (size_t)t * D_;
    __shared__ float hv[D_];
    __shared__ float red[256];
    float ss = 0.f;
    for (int d = tid; d < D_; d += 256) { float v = x[d]; ss += v * v; }
    red[tid] = ss; __syncthreads();
    for (int s = 128; s > 0; s >>= 1) {
        if (tid < s) red[tid] += red[tid + s];
        __syncthreads();
    }
    float scale = rsqrtf(red[0] * (1.f / D_) + 1e-6f);
    for (int d = tid; d < D_; d += 256) {
        float v = x[d] * scale * W[d];
        hv[d] = v;
        OT[(size_t)t * D_ + d] = __float2half_rn(v);
    }
    __syncthreads();

    int e = tid >> 5, lane = tid & 31;
    float p = 0.f;
    for (int d = lane; d < D_; d += 32) p += hv[d] * RW[d * E_ + e];
    for (int o = 16; o > 0; o >>= 1) p += __shfl_down_sync(0xffffffff, p, o);
    __shared__ float lg[E_];
    if (lane == 0) lg[e] = p;
    __syncthreads();
    if (tid == 0) {
        float mx = lg[0];
        for (int i = 1; i < E_; i++) mx = fmaxf(mx, lg[i]);
        float pr[E_]; float s = 0.f;
        for (int i = 0; i < E_; i++) { pr[i] = expf(lg[i] - mx); s += pr[i]; }
        float inv = 1.f / s;
        float b1v = -1.f, b2v = -1.f; int b1i = 0, b2i = 0;
        for (int i = 0; i < E_; i++) {
            float v = pr[i] * inv;
            atomicAdd(&g_probsum[i], v);
            if (v > b1v) { b2v = b1v; b2i = b1i; b1v = v; b1i = i; }
            else if (v > b2v) { b2v = v; b2i = i; }
        }
        g_topidx[t * 2] = b1i; g_topidx[t * 2 + 1] = b2i;
        g_topval[t * 2] = b1v; g_topval[t * 2 + 1] = b2v;
        atomicAdd(&g_counts[b1i], 1);
        atomicAdd(&g_counts[b2i], 1);
    }
}

__global__ void place1_kernel() {
    if (threadIdx.x == 0) {
        int o = 0;
        for (int e = 0; e < E_; e++) {
            g_offs[e] = o;
            g_cursor[e] = o;
            o += g_counts[e];
        }
        g_offs[E_] = o;
    }
    __syncthreads();
    for (int t = threadIdx.x; t < NTOK; t += 1024) {
        for (int kk = 0; kk < KSEL; kk++) {
            int e = g_topidx[t * 2 + kk];
            int slot = atomicAdd(&g_cursor[e], 1);
            g_perm[slot] = t;
            g_slotof[t * 2 + kk] = slot;
        }
    }
}

__global__ void combine_kernel(float* __restrict__ out) {
    int i = blockIdx.x * blockDim.x + threadIdx.x;
    if (i >= NTOK * D_ / 2) return;
    int t = i >> 9, d2 = i & 511;
    float2 v = ((const float2*)g_x2)[i];
    float w0 = g_topval[t * 2], w1 = g_topval[t * 2 + 1];
    __half2 y0 = ((const __half2*)(g_y + (size_t)g_slotof[t * 2] * D_))[d2];
    __half2 y1 = ((const __half2*)(g_y + (size_t)g_slotof[t * 2 + 1] * D_))[d2];
    float2 f0 = __half22float2(y0), f1 = __half22float2(y1);
    v.x += w0 * f0.x + w1 * f1.x;
    v.y += w0 * f0.y + w1 * f1.y;
    ((float2*)out)[i] = v;
}
__global__ void finalize_kernel(float* __restrict__ out) {
    if (threadIdx.x == 0) {
        float loss = 0.f;
        for (int e = 0; e < E_; e++)
            loss += ((float)g_counts[e] / (float)NSLOT) * (g_probsum[e] / (float)NTOK);
        loss *= (float)E_;
        out[(size_t)NTOK * D_] = loss;
        for (int e = 0; e < E_; e++)
            out[(size_t)NTOK * D_ + 1 + e] = (float)g_counts[e];
    }
}

// EPI: 0 half; 1 float + residual; 2 float; 3 half exp causal + atomic rowsum;
// 4 half v / rowsum. mode: 0 none, 1 causal tile-skip, 2 k-clip (heavy-first).
template <bool TB, int NT, int EPI>
__global__ void __launch_bounds__(128, 2)
hgemm(const __half* __restrict__ A, int lda,
      const __half* __restrict__ B, int ldb,
      void* __restrict__ Cv, int ldc,
      int M, int N, int K,
      long long aO, long long aI, long long bO, long long bI,
      long long cO, long long cI, int zdiv,
      float* __restrict__ addpF, int mode) {
    constexpr int BSTH = NT + 8;
    constexpr int BSZB = TB ? ASZB : (64 * BSTH * 2);
    constexpr int STG  = ASZB + BSZB;
    constexpr int NTW  = NT / 16;
    extern __shared__ __align__(16) unsigned char smraw[];

    int z = blockIdx.z, zo = z / zdiv, zi = z % zdiv;
    A += zo * aO + zi * aI;
    B += zo * bO + zi * bI;

    int by = mode ? ((int)gridDim.y - 1 - (int)blockIdx.y) : (int)blockIdx.y;
    int m0 = by * 128, n0 = blockIdx.x * NT;
    if (mode == 1 && n0 > m0 + 127) return;
    int Keff = (mode == 2) ? min(K, m0 + 128) : K;
    int KT = Keff / BKH;

    int tid = threadIdx.x, wid = tid >> 5, lane = tid & 31;
    int warpM = wid & 1, warpN = wid >> 1;
    int g = lane >> 2, t = lane & 3;
    unsigned smb = (unsigned)__cvta_generic_to_shared(smraw);

    bool av = (m0 + tid) < M;
    const __half* aptr = A + (size_t)(av ? (m0 + tid) : 0) * lda;
    const __half* bptr = nullptr;
    bool bv = true;
    if (TB) {
        bv = (n0 + tid) < N;
        bptr = B + (size_t)(bv ? (n0 + tid) : 0) * ldb;
    }

    float acc[4][NTW][4];
#pragma unroll
    for (int mt = 0; mt < 4; mt++)
#pragma unroll
        for (int nt = 0; nt < NTW; nt++)
#pragma unroll
            for (int r = 0; r < 4; r++) acc[mt][nt][r] = 0.f;

    auto issue = [&](int lt) {
        int s = lt % NSTG;
        unsigned ab = smb + (unsigned)s * STG;
        const __half* as = aptr + lt * BKH;
        unsigned arow = ab + (unsigned)tid * (ASTH * 2);
#pragma unroll
        for (int c = 0; c < 8; c++)
            cpa16(arow + c * 16, as + c * 8, av);
        unsigned bb = ab + ASZB;
        if (TB) {
            const __half* bs = bptr + lt * BKH;
            unsigned br = bb + (unsigned)tid * (ASTH * 2);
#pragma unroll
            for (int c = 0; c < 8; c++)
                cpa16(br + c * 16, bs + c * 8, bv);
        } else {
            int row = tid >> 1;
            int cb = (tid & 1) * (NT / 16);
            const __half* bs = B + (size_t)(lt * BKH + row) * ldb + n0;
            unsigned br = bb + (unsigned)row * (BSTH * 2);
#pragma unroll
            for (int j = 0; j < NT / 16; j++)
                cpa16(br + (cb + j) * 16, bs + (cb + j) * 8, true);
        }
        cp_commit();
    };

#pragma unroll
    for (int i = 0; i < NSTG - 1; i++) {
        if (i < KT) issue(i); else cp_commit();
    }

    for (int kt = 0; kt < KT; kt++) {
        int b = kt % NSTG;
        asm volatile("cp.async.wait_group %0;\n" :: "n"(NSTG - 2));
        __syncthreads();

        unsigned aBase = smb + (unsigned)b * STG;
        unsigned bBase = aBase + ASZB;
#pragma unroll
        for (int ks = 0; ks < 4; ks++) {
            unsigned afr[4][4];
#pragma unroll
            for (int mt = 0; mt < 4; mt++) {
                int row = warpM * 64 + mt * 16 + (lane & 15);
                int kh = ks * 16 + ((lane >> 4) << 3);
                ldsm4(afr[mt][0], afr[mt][1], afr[mt][2], afr[mt][3],
                      aBase + (unsigned)(row * ASTH + kh) * 2);
            }
            unsigned bfr[NTW][2];
#pragma unroll
            for (int ntp = 0; ntp < NTW / 2; ntp++) {
                unsigned r0, r1, r2, r3;
                if (TB) {
                    int row = warpN * 64 + ntp * 16 + (lane & 15);
                    int kh = ks * 16 + ((lane >> 4) << 3);
                    ldsm4(r0, r1, r2, r3, bBase + (unsigned)(row * ASTH + kh) * 2);
                    bfr[2 * ntp][0] = r0; bfr[2 * ntp + 1][0] = r1;
                    bfr[2 * ntp][1] = r2; bfr[2 * ntp + 1][1] = r3;
                } else {
                    int krow = ks * 16 + (lane & 15);
                    int col = warpN * (NT / 2) + ntp * 16 + ((lane >> 4) << 3);
                    ldsm4t(r0, r1, r2, r3, bBase + (unsigned)(krow * BSTH + col) * 2);
                    bfr[2 * ntp][0] = r0; bfr[2 * ntp][1] = r1;
                    bfr[2 * ntp + 1][0] = r2; bfr[2 * ntp + 1][1] = r3;
                }
            }
#pragma unroll
            for (int mt = 0; mt < 4; mt++)
#pragma unroll
                for (int nt = 0; nt < NTW; nt++)
                    mma16816(acc[mt][nt], afr[mt], bfr[nt]);
        }
        if (kt + NSTG - 1 < KT) issue(kt + NSTG - 1); else cp_commit();
    }

#pragma unroll
    for (int mt = 0; mt < 4; mt++) {
#pragma unroll
        for (int half_ = 0; half_ < 2; half_++) {
            int r = m0 + warpM * 64 + mt * 16 + g + half_ * 8;
            float rsum = 0.f;
#pragma unroll
            for (int nt = 0; nt < NTW; nt++) {
                int col = n0 + warpN * (NT / 2) + nt * 8 + 2 * t;
                if (r < M && col < N) {
                    float v0 = acc[mt][nt][half_ * 2 + 0];
                    float v1 = acc[mt][nt][half_ * 2 + 1];
                    size_t cidx = (size_t)(zo * cO + zi * cI) + (size_t)r * ldc + col;
                    if (EPI == 0) {
                        *(__half2*)((__half*)Cv + cidx) = __floats2half2_rn(v0, v1);
                    } else if (EPI == 1) {
                        float2 ad = *(const float2*)(addpF + (size_t)r * ldc + col);
                        float2 o; o.x = v0 + ad.x; o.y = v1 + ad.y;
                        *(float2*)((float*)Cv + cidx) = o;
                    } else if (EPI == 2) {
                        float2 o; o.x = v0; o.y = v1;
                        *(float2*)((float*)Cv + cidx) = o;
                    } else if (EPI == 3) {
                        float e0 = (col     <= r) ? __expf(v0 * 0.125f) : 0.f;
                        float e1 = (col + 1 <= r) ? __expf(v1 * 0.125f) : 0.f;
                        rsum += e0 + e1;
                        *(__half2*)((__half*)Cv + cidx) = __floats2half2_rn(e0, e1);
                    } else {
                        float sc = 1.f / addpF[(size_t)z * S_ + r];
                        *(__half2*)((__half*)Cv + cidx) = __floats2half2_rn(v0 * sc, v1 * sc);
                    }
                }
            }
            if (EPI == 3) {
                rsum += __shfl_down_sync(0xffffffffu, rsum, 2);
                rsum += __shfl_down_sync(0xffffffffu, rsum, 1);
                if (t == 0 && r < M)
                    atomicAdd(&addpF[(size_t)z * S_ + r], rsum);
            }
        }
    }
}

// grouped MoE: 256 thr, 128x256, 4-stage, single-sync mainloop.
// e0: expert-group base (blockIdx.z covers EGRP experts starting at e0).
template <int EP>
__global__ void __launch_bounds__(256, 1)
moe_hgemm(const __half* __restrict__ H, const __half* __restrict__ W,
          const float* __restrict__ Bias, int Kdim, int Ndim, int e0) {
    constexpr int BSTH = 264;
    constexpr int BSZB = 64 * BSTH * 2;
    constexpr int STG  = ASZB + BSZB;
    extern __shared__ __align__(16) unsigned char smraw[];

    int e = blockIdx.z + e0;
    int base = g_offs[e], cnt = g_offs[e + 1] - base;
    int m0 = blockIdx.y * 128;
    if (m0 >= cnt) return;
    int n0 = blockIdx.x * 256;
    const __half* Bmat = W + (size_t)e * (size_t)Kdim * Ndim;

    int tid = threadIdx.x, wid = tid >> 5, lane = tid & 31;
    int warpM = wid & 1, warpN = wid >> 1;
    int g = lane >> 2, t = lane & 3;
    unsigned smb = (unsigned)__cvta_generic_to_shared(smraw);
    float* sBias = (float*)smraw;
    unsigned tb0 = smb + 1024;

    sBias[tid] = Bias[(size_t)e * Ndim + n0 + tid];

    int arow_i = tid >> 1;
    bool av = (m0 + arow_i) < cnt;
    const __half* aptr;
    if (EP == 1) aptr = H + (size_t)(av ? g_perm[base + m0 + arow_i] : 0) * Kdim;
    else         aptr = g_act + (size_t)(av ? (base + m0 + arow_i) : 0) * Kdim;
    int ahalf = (tid & 1) * 32;

    int brow = tid >> 2, bq = tid & 3;

    float acc[4][8][4];
#pragma unroll
    for (int mt = 0; mt < 4; mt++)
#pragma unroll
        for (int nt = 0; nt < 8; nt++)
#pragma unroll
            for (int r = 0; r < 4; r++) acc[mt][nt][r] = 0.f;

    int KT = Kdim / BKH;

    auto issue = [&](int lt) {
        int s = lt % MSTG;
        unsigned ab = tb0 + (unsigned)s * STG;
        const __half* as = aptr + lt * BKH + ahalf;
        unsigned ar = ab + (unsigned)arow_i * (ASTH * 2) + (unsigned)(tid & 1) * 64;
#pragma unroll
        for (int c = 0; c < 4; c++)
            cpa16(ar + c * 16, as + c * 8, av);
        unsigned bb = ab + ASZB;
        const __half* bs = Bmat + (size_t)(lt * BKH + brow) * Ndim + n0 + bq * 64;
        unsigned br = bb + (unsigned)brow * (BSTH * 2) + (unsigned)bq * 128;
#pragma unroll
        for (int c = 0; c < 8; c++)
            cpa16(br + c * 16, bs + c * 8, true);
        cp_commit();
    };

#pragma unroll
    for (int i = 0; i < MSTG - 1; i++) {
        if (i < KT) issue(i); else cp_commit();
    }

    for (int kt = 0; kt < KT; kt++) {
        int b = kt % MSTG;
        asm volatile("cp.async.wait_group %0;\n" :: "n"(MSTG - 2));
        __syncthreads();

        unsigned aBase = tb0 + (unsigned)b * STG;
        unsigned bBase = aBase + ASZB;
#pragma unroll
        for (int ks = 0; ks < 4; ks++) {
            unsigned afr[4][4];
#pragma unroll
            for (int mt = 0; mt < 4; mt++) {
                int row = warpM * 64 + mt * 16 + (lane & 15);
                int kh = ks * 16 + ((lane >> 4) << 3);
                ldsm4(afr[mt][0], afr[mt][1], afr[mt][2], afr[mt][3],
                      aBase + (unsigned)(row * ASTH + kh) * 2);
            }
            unsigned bfr[8][2];
#pragma unroll
            for (int ntp = 0; ntp < 4; ntp++) {
                unsigned r0, r1, r2, r3;
                int krow = ks * 16 + (lane & 15);
                int col = warpN * 64 + ntp * 16 + ((lane >> 4) << 3);
                ldsm4t(r0, r1, r2, r3, bBase + (unsigned)(krow * BSTH + col) * 2);
                bfr[2 * ntp][0] = r0; bfr[2 * ntp][1] = r1;
                bfr[2 * ntp + 1][0] = r2; bfr[2 * ntp + 1][1] = r3;
            }
#pragma unroll
            for (int mt = 0; mt < 4; mt++)
#pragma unroll
                for (int nt = 0; nt < 8; nt++)
                    mma16816(acc[mt][nt], afr[mt], bfr[nt]);
        }
        if (kt + MSTG - 1 < KT) issue(kt + MSTG - 1); else cp_commit();
    }

#pragma unroll
    for (int mt = 0; mt < 4; mt++) {
#pragma unroll
        for (int nt = 0; nt < 8; nt++) {
            int rr = m0 + warpM * 64 + mt * 16 + g;
            int colL = warpN * 64 + nt * 8 + 2 * t;
            int col = n0 + colL;
#pragma unroll
            for (int half_ = 0; half_ < 2; half_++) {
                int r = rr + half_ * 8;
                if (r < cnt) {
                    float v0 = acc[mt][nt][half_ * 2 + 0] + sBias[colL];
                    float v1 = acc[mt][nt][half_ * 2 + 1] + sBias[colL + 1];
                    if (EP == 1) {
                        *(__half2*)(g_act + (size_t)(base + r) * FF_ + col) =
                            __floats2half2_rn(gelu_tanh(v0), gelu_tanh(v1));
                    } else {
                        *(__half2*)(g_y + (size_t)(base + r) * D_ + col) =
                            __floats2half2_rn(v0, v1);
                    }
                }
            }
        }
    }
}

#define SMEM_NF128 (NSTG * (ASZB + 64 * 136 * 2))
#define SMEM_T128  (NSTG * (ASZB + ASZB))
#define SMEM_NF64  (NSTG * (ASZB + 64 * 72 * 2))
#define SMEM_MOE   (1024 + MSTG * (ASZB + 64 * 264 * 2))
#define EGRP       4

extern "C" void kernel_launch(void* const* d_in, const int* in_sizes, int n_in,
                              void* d_out, int out_size) {
    const float* x   = (const float*)d_in[0];
    const float* anw = (const float*)d_in[1];
    const float* wq  = (const float*)d_in[2];
    const float* wk  = (const float*)d_in[3];
    const float* wv  = (const float*)d_in[4];
    const float* wo  = (const float*)d_in[5];
    const float* mnw = (const float*)d_in[6];
    const float* rw  = (const float*)d_in[7];
    const float* w1  = (const float*)d_in[8];
    const float* b1  = (const float*)d_in[9];
    const float* w2  = (const float*)d_in[10];
    const float* b2  = (const float*)d_in[11];
    float* out = (float*)d_out;

    cudaFuncSetAttribute(hgemm<false, 128, 0>, cudaFuncAttributeMaxDynamicSharedMemorySize, SMEM_NF128);
    cudaFuncSetAttribute(hgemm<false, 128, 1>, cudaFuncAttributeMaxDynamicSharedMemorySize, SMEM_NF128);
    cudaFuncSetAttribute(hgemm<true, 128, 3>,  cudaFuncAttributeMaxDynamicSharedMemorySize, SMEM_T128);
    cudaFuncSetAttribute(hgemm<false, 64, 4>,  cudaFuncAttributeMaxDynamicSharedMemorySize, SMEM_NF64);
    cudaFuncSetAttribute(moe_hgemm<1>,         cudaFuncAttributeMaxDynamicSharedMemorySize, SMEM_MOE);
    cudaFuncSetAttribute(moe_hgemm<2>,         cudaFuncAttributeMaxDynamicSharedMemorySize, SMEM_MOE);

    __half *xn, *wqkvh, *woh, *w1h, *w2h, *qkv, *probsH, *ao, *htf;
    float *x2, *rsum;
    cudaGetSymbolAddress((void**)&xn,     g_xn);
    cudaGetSymbolAddress((void**)&wqkvh,  g_wqkvh);
    cudaGetSymbolAddress((void**)&woh,    g_woh);
    cudaGetSymbolAddress((void**)&w1h,    g_w1h);
    cudaGetSymbolAddress((void**)&w2h,    g_w2h);
    cudaGetSymbolAddress((void**)&qkv,    g_qkv);
    cudaGetSymbolAddress((void**)&probsH, g_probsH);
    cudaGetSymbolAddress((void**)&rsum,   g_rowsum);
    cudaGetSymbolAddress((void**)&ao,     g_attnout);
    cudaGetSymbolAddress((void**)&x2,     g_x2);
    cudaGetSymbolAddress((void**)&htf,    g_htf);

    const __half* q = qkv;
    const __half* k = qkv + (size_t)NTOK * D_;
    const __half* v = qkv + 2 * (size_t)NTOK * D_;

    cudaStream_t s2;
    cudaEvent_t evFork, evQW, evJoin1, evJoin2, evPlace, evM2b;
    cudaStreamCreateWithFlags(&s2, cudaStreamNonBlocking);
    cudaEventCreateWithFlags(&evFork, cudaEventDisableTiming);
    cudaEventCreateWithFlags(&evQW, cudaEventDisableTiming);
    cudaEventCreateWithFlags(&evJoin1, cudaEventDisableTiming);
    cudaEventCreateWithFlags(&evJoin2, cudaEventDisableTiming);
    cudaEventCreateWithFlags(&evPlace, cudaEventDisableTiming);
    cudaEventCreateWithFlags(&evM2b, cudaEventDisableTiming);

    init2_kernel<<<(BB_ * NH_ * S_ + 511) / 512, 512>>>();
    cudaEventRecord(evFork, 0);
    cudaStreamWaitEvent(s2, evFork, 0);

    // side stream: QKV/WO converts first, then big MoE converts
    f2h4_kernel<<<dim3(256, 4), 256, 0, s2>>>((const float4*)wq, (const float4*)wk,
                                              (const float4*)wv, (const float4*)wo,
                                              (uint4*)wqkvh, (uint4*)woh);
    cudaEventRecord(evQW, s2);
    f2h_kernel<<<4096, 256, 0, s2>>>((const float4*)w1, (uint4*)w1h, (long long)E_ * D_ * FF_ / 8);
    cudaEventRecord(evJoin1, s2);
    f2h_kernel<<<4096, 256, 0, s2>>>((const float4*)w2, (uint4*)w2h, (long long)E_ * FF_ * D_ / 8);
    cudaEventRecord(evJoin2, s2);

    // main: attention chain (rmsnorm overlaps f2h4)
    rmsnorm_kernel<<<NTOK, 256>>>(x, anw, xn);
    cudaStreamWaitEvent(0, evQW, 0);

    hgemm<false, 128, 0><<<dim3(8, 16, 3), 128, SMEM_NF128>>>(
        xn, D_, wqkvh, D_, qkv, D_, NTOK, D_, D_,
        0, 0, (long long)D_ * D_, 0, (long long)NTOK * D_, 0, 1, nullptr, 0);

    {
        long long sSD = (long long)S_ * D_, sSS = (long long)S_ * S_;
        hgemm<true, 128, 3><<<dim3(8, 8, BB_ * NH_), 128, SMEM_T128>>>(
            q, D_, k, D_, probsH, S_, S_, S_, DH_,
            sSD, DH_, sSD, DH_, NH_ * sSS, sSS, NH_, rsum, 1);
    }

    {
        long long sSD = (long long)S_ * D_, sSS = (long long)S_ * S_;
        hgemm<false, 64, 4><<<dim3(1, 8, BB_ * NH_), 128, SMEM_NF64>>>(
            probsH, S_, v, D_, ao, D_, S_, DH_, S_,
            NH_ * sSS, sSS, sSD, DH_, sSD, DH_, NH_, rsum, 2);
    }

    hgemm<false, 128, 1><<<dim3(8, 16, 1), 128, SMEM_NF128>>>(
        ao, D_, woh, D_, x2, D_, NTOK, D_, D_,
        0, 0, 0, 0, 0, 0, 1, (float*)x, 0);

    rmsrouter_kernel<<<NTOK, 256>>>(x2, mnw, htf, rw);
    place1_kernel<<<1, 1024>>>();
    cudaEventRecord(evPlace, 0);

    // expert-split MoE: main does experts 0-3 (gemm1 then gemm2);
    // side stream does experts 4-7 concurrently (its f2h chain is already done
    // in-order, so it has w1h/w2h; it only needs routing via evPlace).
    cudaStreamWaitEvent(s2, evPlace, 0);
    moe_hgemm<1><<<dim3(FF_ / 256, NSLOT / 128, EGRP), 256, SMEM_MOE, s2>>>(htf, w1h, b1, D_, FF_, EGRP);
    moe_hgemm<2><<<dim3(D_ / 256, NSLOT / 128, EGRP), 256, SMEM_MOE, s2>>>(nullptr, w2h, b2, FF_, D_, EGRP);
    cudaEventRecord(evM2b, s2);

    cudaStreamWaitEvent(0, evJoin1, 0);
    moe_hgemm<1><<<dim3(FF_ / 256, NSLOT / 128, EGRP), 256, SMEM_MOE>>>(htf, w1h, b1, D_, FF_, 0);
    cudaStreamWaitEvent(0, evJoin2, 0);
    moe_hgemm<2><<<dim3(D_ / 256, NSLOT / 128, EGRP), 256, SMEM_MOE>>>(nullptr, w2h, b2, FF_, D_, 0);

    cudaStreamWaitEvent(0, evM2b, 0);
    combine_kernel<<<(NTOK * D_ / 2 + 255) / 256, 256>>>(out);
    finalize_kernel<<<1, 32>>>(out);
}